// round 1
// baseline (speedup 1.0000x reference)
#include <cuda_runtime.h>

// StyleLoss: loss = sum_{k=1..5} sqrt( sum_c (mu_k_x[c] - mu_k_y[c])^2 )
// where mu_1 is the per-channel mean and mu_k (k>=2) the k-th central moment
// over axes (B,H,W). Shape fixed: (8, 256, 128, 128) fp32.
//
// Single pass over both tensors computing raw moments E[x^k], k=1..5 per
// channel; central moments recovered via binomial identities in double.

#define NCHAN   256
#define NB      8
#define HW      (128 * 128)          // 16384 contiguous floats per (b,c) slab
#define NBLK    (NCHAN * NB)         // 2048 blocks
#define NPERCH  ((double)(NB * HW))  // 131072 elements per channel

__device__ float g_partial[NBLK * 10];

#define ACC(v)                                   \
    do {                                         \
        float _v  = (v);                         \
        float _v2 = _v * _v;                     \
        float _v3 = _v2 * _v;                    \
        float _v4 = _v2 * _v2;                   \
        s0 += _v;  s1 += _v2; s2 += _v3;         \
        s3 += _v4; s4 += _v4 * _v;               \
    } while (0)

#define ACCY(v)                                  \
    do {                                         \
        float _v  = (v);                         \
        float _v2 = _v * _v;                     \
        float _v3 = _v2 * _v;                    \
        float _v4 = _v2 * _v2;                   \
        t0 += _v;  t1 += _v2; t2 += _v3;         \
        t3 += _v4; t4 += _v4 * _v;               \
    } while (0)

__global__ __launch_bounds__(256, 8)
void k_moments(const float* __restrict__ x, const float* __restrict__ y) {
    const int bid = blockIdx.x;
    const int c = bid >> 3;          // channel
    const int b = bid & 7;           // batch
    const size_t base = ((size_t)b * NCHAN + (size_t)c) * HW;
    const float4* __restrict__ xp = reinterpret_cast<const float4*>(x + base);
    const float4* __restrict__ yp = reinterpret_cast<const float4*>(y + base);

    const int tid = threadIdx.x;

    float s0 = 0.f, s1 = 0.f, s2 = 0.f, s3 = 0.f, s4 = 0.f;  // x moments
    float t0 = 0.f, t1 = 0.f, t2 = 0.f, t3 = 0.f, t4 = 0.f;  // y moments

    // 4096 float4 per slab per tensor; 256 threads -> 16 float4 each.
    #pragma unroll
    for (int i = 0; i < 16; ++i) {
        float4 xv = xp[tid + (i << 8)];
        float4 yv = yp[tid + (i << 8)];
        ACC(xv.x); ACC(xv.y); ACC(xv.z); ACC(xv.w);
        ACCY(yv.x); ACCY(yv.y); ACCY(yv.z); ACCY(yv.w);
    }

    // Warp reduce all 10 accumulators.
    #pragma unroll
    for (int o = 16; o > 0; o >>= 1) {
        s0 += __shfl_xor_sync(0xffffffffu, s0, o);
        s1 += __shfl_xor_sync(0xffffffffu, s1, o);
        s2 += __shfl_xor_sync(0xffffffffu, s2, o);
        s3 += __shfl_xor_sync(0xffffffffu, s3, o);
        s4 += __shfl_xor_sync(0xffffffffu, s4, o);
        t0 += __shfl_xor_sync(0xffffffffu, t0, o);
        t1 += __shfl_xor_sync(0xffffffffu, t1, o);
        t2 += __shfl_xor_sync(0xffffffffu, t2, o);
        t3 += __shfl_xor_sync(0xffffffffu, t3, o);
        t4 += __shfl_xor_sync(0xffffffffu, t4, o);
    }

    __shared__ float sm[8][10];
    const int w = tid >> 5;
    if ((tid & 31) == 0) {
        sm[w][0] = s0; sm[w][1] = s1; sm[w][2] = s2; sm[w][3] = s3; sm[w][4] = s4;
        sm[w][5] = t0; sm[w][6] = t1; sm[w][7] = t2; sm[w][8] = t3; sm[w][9] = t4;
    }
    __syncthreads();

    if (tid < 10) {
        float a = 0.f;
        #pragma unroll
        for (int ww = 0; ww < 8; ++ww) a += sm[ww][tid];
        g_partial[bid * 10 + tid] = a;
    }
}

__global__ __launch_bounds__(256)
void k_finalize(float* __restrict__ out) {
    const int c = threadIdx.x;   // one thread per channel

    double a[10];
    #pragma unroll
    for (int k = 0; k < 10; ++k) a[k] = 0.0;

    // Partials for channel c live at blocks bid = c*8 + b? No: bid = b*? —
    // kernel1 maps c = bid>>3, b = bid&7, so bid = c*8 + b. Contiguous.
    #pragma unroll
    for (int b = 0; b < NB; ++b) {
        const float* p = &g_partial[(c * NB + b) * 10];
        #pragma unroll
        for (int k = 0; k < 10; ++k) a[k] += (double)p[k];
    }

    const double invN = 1.0 / NPERCH;
    double ax1 = a[0] * invN, ax2 = a[1] * invN, ax3 = a[2] * invN,
           ax4 = a[3] * invN, ax5 = a[4] * invN;
    double ay1 = a[5] * invN, ay2 = a[6] * invN, ay3 = a[7] * invN,
           ay4 = a[8] * invN, ay5 = a[9] * invN;

    // Central moments from raw moments.
    double mx = ax1, my = ay1;
    double mx2 = mx * mx, mx3 = mx2 * mx, mx4 = mx2 * mx2, mx5 = mx4 * mx;
    double my2 = my * my, my3 = my2 * my, my4 = my2 * my2, my5 = my4 * my;

    double ux2 = ax2 - mx2;
    double ux3 = ax3 - 3.0 * mx * ax2 + 2.0 * mx3;
    double ux4 = ax4 - 4.0 * mx * ax3 + 6.0 * mx2 * ax2 - 3.0 * mx4;
    double ux5 = ax5 - 5.0 * mx * ax4 + 10.0 * mx2 * ax3 - 10.0 * mx3 * ax2 + 4.0 * mx5;

    double uy2 = ay2 - my2;
    double uy3 = ay3 - 3.0 * my * ay2 + 2.0 * my3;
    double uy4 = ay4 - 4.0 * my * ay3 + 6.0 * my2 * ay2 - 3.0 * my4;
    double uy5 = ay5 - 5.0 * my * ay4 + 10.0 * my2 * ay3 - 10.0 * my3 * ay2 + 4.0 * my5;

    double d1 = mx - my;
    double d2 = ux2 - uy2;
    double d3 = ux3 - uy3;
    double d4 = ux4 - uy4;
    double d5 = ux5 - uy5;

    double c1 = d1 * d1, c2 = d2 * d2, c3 = d3 * d3, c4 = d4 * d4, c5 = d5 * d5;

    // Block reduce 5 doubles over 256 threads.
    #pragma unroll
    for (int o = 16; o > 0; o >>= 1) {
        c1 += __shfl_xor_sync(0xffffffffu, c1, o);
        c2 += __shfl_xor_sync(0xffffffffu, c2, o);
        c3 += __shfl_xor_sync(0xffffffffu, c3, o);
        c4 += __shfl_xor_sync(0xffffffffu, c4, o);
        c5 += __shfl_xor_sync(0xffffffffu, c5, o);
    }

    __shared__ double sm[8][5];
    const int w = c >> 5;
    if ((c & 31) == 0) {
        sm[w][0] = c1; sm[w][1] = c2; sm[w][2] = c3; sm[w][3] = c4; sm[w][4] = c5;
    }
    __syncthreads();

    if (c == 0) {
        double S1 = 0, S2 = 0, S3 = 0, S4 = 0, S5 = 0;
        #pragma unroll
        for (int ww = 0; ww < 8; ++ww) {
            S1 += sm[ww][0]; S2 += sm[ww][1]; S3 += sm[ww][2];
            S4 += sm[ww][3]; S5 += sm[ww][4];
        }
        double loss = sqrt(S1) + sqrt(S2) + sqrt(S3) + sqrt(S4) + sqrt(S5);
        out[0] = (float)loss;
    }
}

extern "C" void kernel_launch(void* const* d_in, const int* in_sizes, int n_in,
                              void* d_out, int out_size) {
    const float* x = (const float*)d_in[0];
    const float* y = (const float*)d_in[1];
    float* out = (float*)d_out;

    k_moments<<<NBLK, 256>>>(x, y);
    k_finalize<<<1, 256>>>(out);
}

// round 2
// speedup vs baseline: 1.2262x; 1.2262x over previous
#include <cuda_runtime.h>

// StyleLoss: loss = sum_{k=1..5} sqrt( sum_c (mu_k_x[c] - mu_k_y[c])^2 )
// mu_1 = per-channel mean, mu_k (k>=2) = k-th central moment over (B,H,W).
// Shape fixed: (8, 256, 128, 128) fp32.
//
// Pass 1 (k_moments): raw moments E[x^k], k=1..5, per (b,c) slab, using
// packed f32x2 arithmetic (FFMA2/FADD2/FMUL2 — sm_103a packed fp32 pipe,
// only reachable via PTX) so the FMA pipe does half the warp-instructions.
// Pass 2 (k_finalize): fp32 central-moment conversion + RMSE sums.
// (FP64 avoided entirely: sm_103a FP64 pipe is ~18 cyc/op/SM.)

#define NCHAN   256
#define NB      8
#define HW      (128 * 128)          // 16384 contiguous floats per (b,c) slab
#define NBLK    (NCHAN * NB)         // 2048 blocks
#define NPERCH  ((float)(NB * HW))   // 131072 elements per channel

__device__ float g_partial[NBLK * 10];

// ---- packed f32x2 helpers ------------------------------------------------
typedef unsigned long long u64;

#define MUL2(d, a, b) \
    asm("mul.rn.f32x2 %0, %1, %2;" : "=l"(d) : "l"(a), "l"(b))
#define ADD2(d, a, b) \
    asm("add.rn.f32x2 %0, %1, %2;" : "=l"(d) : "l"(a), "l"(b))
#define FMA2(d, a, b, c) \
    asm("fma.rn.f32x2 %0, %1, %2, %3;" : "=l"(d) : "l"(a), "l"(b), "l"(c))
#define PACK2(d, lo, hi) \
    asm("mov.b64 %0, {%1, %2};" : "=l"(d) : "f"(lo), "f"(hi))
#define UNPACK2(lo, hi, s) \
    asm("mov.b64 {%0, %1}, %2;" : "=f"(lo), "=f"(hi) : "l"(s))

// Accumulate packed pair p into packed moment accumulators A1..A5.
// 2 MUL2 + 3 ADD2 + 2 FMA2 = 7 packed ops per 2 elements.
#define ACCP(p, A1, A2, A3, A4, A5)          \
    do {                                     \
        u64 _p2, _p4;                        \
        MUL2(_p2, (p), (p));                 \
        MUL2(_p4, _p2, _p2);                 \
        ADD2(A1, A1, (p));                   \
        ADD2(A2, A2, _p2);                   \
        FMA2(A3, _p2, (p), A3);              \
        ADD2(A4, A4, _p4);                   \
        FMA2(A5, _p4, (p), A5);              \
    } while (0)

__global__ __launch_bounds__(256, 8)
void k_moments(const float* __restrict__ x, const float* __restrict__ y) {
    const int bid = blockIdx.x;
    const int c = bid >> 3;          // channel
    const int b = bid & 7;           // batch
    const size_t base = ((size_t)b * NCHAN + (size_t)c) * HW;
    const float4* __restrict__ xp = reinterpret_cast<const float4*>(x + base);
    const float4* __restrict__ yp = reinterpret_cast<const float4*>(y + base);

    const int tid = threadIdx.x;

    // Packed accumulators: x moments S1..S5, y moments T1..T5 (each = 2 lanes).
    u64 S1 = 0, S2 = 0, S3 = 0, S4 = 0, S5 = 0;
    u64 T1 = 0, T2 = 0, T3 = 0, T4 = 0, T5 = 0;

    // 4096 float4 per slab per tensor; 256 threads -> 16 float4 each.
    #pragma unroll
    for (int i = 0; i < 16; ++i) {
        float4 xv = xp[tid + (i << 8)];
        float4 yv = yp[tid + (i << 8)];
        u64 pa, pb, qa, qb;
        PACK2(pa, xv.x, xv.y);
        PACK2(pb, xv.z, xv.w);
        PACK2(qa, yv.x, yv.y);
        PACK2(qb, yv.z, yv.w);
        ACCP(pa, S1, S2, S3, S4, S5);
        ACCP(pb, S1, S2, S3, S4, S5);
        ACCP(qa, T1, T2, T3, T4, T5);
        ACCP(qb, T1, T2, T3, T4, T5);
    }

    // Collapse packed lanes to scalars.
    float s0, s1, s2, s3, s4, t0, t1, t2, t3, t4;
    {
        float lo, hi;
        UNPACK2(lo, hi, S1); s0 = lo + hi;
        UNPACK2(lo, hi, S2); s1 = lo + hi;
        UNPACK2(lo, hi, S3); s2 = lo + hi;
        UNPACK2(lo, hi, S4); s3 = lo + hi;
        UNPACK2(lo, hi, S5); s4 = lo + hi;
        UNPACK2(lo, hi, T1); t0 = lo + hi;
        UNPACK2(lo, hi, T2); t1 = lo + hi;
        UNPACK2(lo, hi, T3); t2 = lo + hi;
        UNPACK2(lo, hi, T4); t3 = lo + hi;
        UNPACK2(lo, hi, T5); t4 = lo + hi;
    }

    // Warp reduce all 10 accumulators.
    #pragma unroll
    for (int o = 16; o > 0; o >>= 1) {
        s0 += __shfl_xor_sync(0xffffffffu, s0, o);
        s1 += __shfl_xor_sync(0xffffffffu, s1, o);
        s2 += __shfl_xor_sync(0xffffffffu, s2, o);
        s3 += __shfl_xor_sync(0xffffffffu, s3, o);
        s4 += __shfl_xor_sync(0xffffffffu, s4, o);
        t0 += __shfl_xor_sync(0xffffffffu, t0, o);
        t1 += __shfl_xor_sync(0xffffffffu, t1, o);
        t2 += __shfl_xor_sync(0xffffffffu, t2, o);
        t3 += __shfl_xor_sync(0xffffffffu, t3, o);
        t4 += __shfl_xor_sync(0xffffffffu, t4, o);
    }

    __shared__ float sm[8][10];
    const int w = tid >> 5;
    if ((tid & 31) == 0) {
        sm[w][0] = s0; sm[w][1] = s1; sm[w][2] = s2; sm[w][3] = s3; sm[w][4] = s4;
        sm[w][5] = t0; sm[w][6] = t1; sm[w][7] = t2; sm[w][8] = t3; sm[w][9] = t4;
    }
    __syncthreads();

    if (tid < 10) {
        float a = 0.f;
        #pragma unroll
        for (int ww = 0; ww < 8; ++ww) a += sm[ww][tid];
        g_partial[bid * 10 + tid] = a;
    }
}

__global__ __launch_bounds__(256)
void k_finalize(float* __restrict__ out) {
    const int c = threadIdx.x;   // one thread per channel

    float a[10];
    #pragma unroll
    for (int k = 0; k < 10; ++k) a[k] = 0.f;

    // kernel1 maps c = bid>>3, b = bid&7 -> bid = c*8 + b (contiguous per c).
    #pragma unroll
    for (int b = 0; b < NB; ++b) {
        const float* p = &g_partial[(c * NB + b) * 10];
        #pragma unroll
        for (int k = 0; k < 10; ++k) a[k] += p[k];
    }

    const float invN = 1.0f / NPERCH;
    float ax1 = a[0] * invN, ax2 = a[1] * invN, ax3 = a[2] * invN,
          ax4 = a[3] * invN, ax5 = a[4] * invN;
    float ay1 = a[5] * invN, ay2 = a[6] * invN, ay3 = a[7] * invN,
          ay4 = a[8] * invN, ay5 = a[9] * invN;

    // Central moments from raw moments (binomial identities).
    float mx = ax1, my = ay1;
    float mx2 = mx * mx, mx3 = mx2 * mx, mx4 = mx2 * mx2, mx5 = mx4 * mx;
    float my2 = my * my, my3 = my2 * my, my4 = my2 * my2, my5 = my4 * my;

    float ux2 = ax2 - mx2;
    float ux3 = ax3 - 3.0f * mx * ax2 + 2.0f * mx3;
    float ux4 = ax4 - 4.0f * mx * ax3 + 6.0f * mx2 * ax2 - 3.0f * mx4;
    float ux5 = ax5 - 5.0f * mx * ax4 + 10.0f * mx2 * ax3 - 10.0f * mx3 * ax2 + 4.0f * mx5;

    float uy2 = ay2 - my2;
    float uy3 = ay3 - 3.0f * my * ay2 + 2.0f * my3;
    float uy4 = ay4 - 4.0f * my * ay3 + 6.0f * my2 * ay2 - 3.0f * my4;
    float uy5 = ay5 - 5.0f * my * ay4 + 10.0f * my2 * ay3 - 10.0f * my3 * ay2 + 4.0f * my5;

    float d1 = mx - my;
    float d2 = ux2 - uy2;
    float d3 = ux3 - uy3;
    float d4 = ux4 - uy4;
    float d5 = ux5 - uy5;

    float c1 = d1 * d1, c2 = d2 * d2, c3 = d3 * d3, c4 = d4 * d4, c5 = d5 * d5;

    // Block reduce 5 floats over 256 threads.
    #pragma unroll
    for (int o = 16; o > 0; o >>= 1) {
        c1 += __shfl_xor_sync(0xffffffffu, c1, o);
        c2 += __shfl_xor_sync(0xffffffffu, c2, o);
        c3 += __shfl_xor_sync(0xffffffffu, c3, o);
        c4 += __shfl_xor_sync(0xffffffffu, c4, o);
        c5 += __shfl_xor_sync(0xffffffffu, c5, o);
    }

    __shared__ float sm[8][5];
    const int w = c >> 5;
    if ((c & 31) == 0) {
        sm[w][0] = c1; sm[w][1] = c2; sm[w][2] = c3; sm[w][3] = c4; sm[w][4] = c5;
    }
    __syncthreads();

    if (c == 0) {
        float S1 = 0, S2 = 0, S3 = 0, S4 = 0, S5 = 0;
        #pragma unroll
        for (int ww = 0; ww < 8; ++ww) {
            S1 += sm[ww][0]; S2 += sm[ww][1]; S3 += sm[ww][2];
            S4 += sm[ww][3]; S5 += sm[ww][4];
        }
        out[0] = sqrtf(S1) + sqrtf(S2) + sqrtf(S3) + sqrtf(S4) + sqrtf(S5);
    }
}

extern "C" void kernel_launch(void* const* d_in, const int* in_sizes, int n_in,
                              void* d_out, int out_size) {
    const float* x = (const float*)d_in[0];
    const float* y = (const float*)d_in[1];
    float* out = (float*)d_out;

    k_moments<<<NBLK, 256>>>(x, y);
    k_finalize<<<1, 256>>>(out);
}

// round 3
// speedup vs baseline: 1.4207x; 1.1586x over previous
#include <cuda_runtime.h>

// StyleLoss: loss = sum_{k=1..5} sqrt( sum_c (mu_k_x[c] - mu_k_y[c])^2 )
// mu_1 = per-channel mean, mu_k (k>=2) = k-th central moment over (B,H,W).
// Shape fixed: (8, 256, 128, 128) fp32.
//
// SINGLE kernel: each of 2048 blocks computes raw-moment sums E-hat[x^k],
// k=1..5, for one (b,c) slab (packed f32x2 math), writes 10 partials in a
// k-major (transposed) layout, then the LAST block to finish (atomic ticket,
// threadFenceReduction pattern) reduces over b, converts raw->central
// moments, and emits the loss. Counter is reset by the finalizer so the
// kernel is graph-replay safe.

#define NCHAN   256
#define NB      8
#define HW      (128 * 128)          // 16384 contiguous floats per (b,c) slab
#define NBLK    (NCHAN * NB)         // 2048 blocks
#define NPERCH  ((float)(NB * HW))   // 131072 elements per channel

__device__ float g_partial[10 * NBLK];   // [k][bid]
__device__ int   g_count = 0;

// ---- packed f32x2 helpers ------------------------------------------------
typedef unsigned long long u64;

#define MUL2(d, a, b) \
    asm("mul.rn.f32x2 %0, %1, %2;" : "=l"(d) : "l"(a), "l"(b))
#define ADD2(d, a, b) \
    asm("add.rn.f32x2 %0, %1, %2;" : "=l"(d) : "l"(a), "l"(b))
#define FMA2(d, a, b, c) \
    asm("fma.rn.f32x2 %0, %1, %2, %3;" : "=l"(d) : "l"(a), "l"(b), "l"(c))
#define PACK2(d, lo, hi) \
    asm("mov.b64 %0, {%1, %2};" : "=l"(d) : "f"(lo), "f"(hi))
#define UNPACK2(lo, hi, s) \
    asm("mov.b64 {%0, %1}, %2;" : "=f"(lo), "=f"(hi) : "l"(s))

// 2 MUL2 + 3 ADD2 + 2 FMA2 = 7 packed ops per 2 elements.
#define ACCP(p, A1, A2, A3, A4, A5)          \
    do {                                     \
        u64 _p2, _p4;                        \
        MUL2(_p2, (p), (p));                 \
        MUL2(_p4, _p2, _p2);                 \
        ADD2(A1, A1, (p));                   \
        ADD2(A2, A2, _p2);                   \
        FMA2(A3, _p2, (p), A3);              \
        ADD2(A4, A4, _p4);                   \
        FMA2(A5, _p4, (p), A5);              \
    } while (0)

__global__ __launch_bounds__(256)
void k_style(const float* __restrict__ x, const float* __restrict__ y,
             float* __restrict__ out) {
    const int bid = blockIdx.x;
    const int c = bid >> 3;          // channel
    const int b = bid & 7;           // batch
    const size_t base = ((size_t)b * NCHAN + (size_t)c) * HW;
    const float4* __restrict__ xp = reinterpret_cast<const float4*>(x + base);
    const float4* __restrict__ yp = reinterpret_cast<const float4*>(y + base);

    const int tid = threadIdx.x;

    u64 S1 = 0, S2 = 0, S3 = 0, S4 = 0, S5 = 0;   // x raw-moment sums (2 lanes)
    u64 T1 = 0, T2 = 0, T3 = 0, T4 = 0, T5 = 0;   // y raw-moment sums

    // 4096 float4 per slab per tensor; 256 threads -> 16 float4 each.
    // __ldcs: stream (read-once working set 2x the L2).
    #pragma unroll
    for (int i = 0; i < 16; ++i) {
        float4 xv = __ldcs(xp + tid + (i << 8));
        float4 yv = __ldcs(yp + tid + (i << 8));
        u64 pa, pb, qa, qb;
        PACK2(pa, xv.x, xv.y);
        PACK2(pb, xv.z, xv.w);
        PACK2(qa, yv.x, yv.y);
        PACK2(qb, yv.z, yv.w);
        ACCP(pa, S1, S2, S3, S4, S5);
        ACCP(pb, S1, S2, S3, S4, S5);
        ACCP(qa, T1, T2, T3, T4, T5);
        ACCP(qb, T1, T2, T3, T4, T5);
    }

    // Collapse packed lanes to scalars.
    float s0, s1, s2, s3, s4, t0, t1, t2, t3, t4;
    {
        float lo, hi;
        UNPACK2(lo, hi, S1); s0 = lo + hi;
        UNPACK2(lo, hi, S2); s1 = lo + hi;
        UNPACK2(lo, hi, S3); s2 = lo + hi;
        UNPACK2(lo, hi, S4); s3 = lo + hi;
        UNPACK2(lo, hi, S5); s4 = lo + hi;
        UNPACK2(lo, hi, T1); t0 = lo + hi;
        UNPACK2(lo, hi, T2); t1 = lo + hi;
        UNPACK2(lo, hi, T3); t2 = lo + hi;
        UNPACK2(lo, hi, T4); t3 = lo + hi;
        UNPACK2(lo, hi, T5); t4 = lo + hi;
    }

    // Warp reduce all 10 accumulators.
    #pragma unroll
    for (int o = 16; o > 0; o >>= 1) {
        s0 += __shfl_xor_sync(0xffffffffu, s0, o);
        s1 += __shfl_xor_sync(0xffffffffu, s1, o);
        s2 += __shfl_xor_sync(0xffffffffu, s2, o);
        s3 += __shfl_xor_sync(0xffffffffu, s3, o);
        s4 += __shfl_xor_sync(0xffffffffu, s4, o);
        t0 += __shfl_xor_sync(0xffffffffu, t0, o);
        t1 += __shfl_xor_sync(0xffffffffu, t1, o);
        t2 += __shfl_xor_sync(0xffffffffu, t2, o);
        t3 += __shfl_xor_sync(0xffffffffu, t3, o);
        t4 += __shfl_xor_sync(0xffffffffu, t4, o);
    }

    __shared__ float smr[8][10];
    const int w = tid >> 5;
    if ((tid & 31) == 0) {
        smr[w][0] = s0; smr[w][1] = s1; smr[w][2] = s2; smr[w][3] = s3; smr[w][4] = s4;
        smr[w][5] = t0; smr[w][6] = t1; smr[w][7] = t2; smr[w][8] = t3; smr[w][9] = t4;
    }
    __syncthreads();

    if (tid < 10) {
        float a = 0.f;
        #pragma unroll
        for (int ww = 0; ww < 8; ++ww) a += smr[ww][tid];
        // k-major layout: channel c's 8 batch-partials for moment k are the
        // 8 contiguous floats at g_partial[k*NBLK + c*8].
        g_partial[tid * NBLK + bid] = a;
    }

    // ---- last-block finalize (threadFenceReduction pattern) --------------
    __shared__ int is_last;
    __threadfence();
    __syncthreads();
    if (tid == 0) {
        int v = atomicAdd(&g_count, 1);
        is_last = (v == NBLK - 1) ? 1 : 0;
    }
    __syncthreads();
    if (!is_last) return;

    // This block runs after every other block's partials are globally visible.
    const int ch = tid;              // one thread per channel

    float a[10];
    #pragma unroll
    for (int k = 0; k < 10; ++k) {
        const float4* p =
            reinterpret_cast<const float4*>(&g_partial[k * NBLK + ch * 8]);
        float4 u = p[0];
        float4 v = p[1];
        a[k] = ((u.x + u.y) + (u.z + u.w)) + ((v.x + v.y) + (v.z + v.w));
    }

    const float invN = 1.0f / NPERCH;
    float ax1 = a[0] * invN, ax2 = a[1] * invN, ax3 = a[2] * invN,
          ax4 = a[3] * invN, ax5 = a[4] * invN;
    float ay1 = a[5] * invN, ay2 = a[6] * invN, ay3 = a[7] * invN,
          ay4 = a[8] * invN, ay5 = a[9] * invN;

    // Central moments from raw moments (binomial identities).
    float mx = ax1, my = ay1;
    float mx2 = mx * mx, mx3 = mx2 * mx, mx4 = mx2 * mx2, mx5 = mx4 * mx;
    float my2 = my * my, my3 = my2 * my, my4 = my2 * my2, my5 = my4 * my;

    float ux2 = ax2 - mx2;
    float ux3 = ax3 - 3.0f * mx * ax2 + 2.0f * mx3;
    float ux4 = ax4 - 4.0f * mx * ax3 + 6.0f * mx2 * ax2 - 3.0f * mx4;
    float ux5 = ax5 - 5.0f * mx * ax4 + 10.0f * mx2 * ax3 - 10.0f * mx3 * ax2 + 4.0f * mx5;

    float uy2 = ay2 - my2;
    float uy3 = ay3 - 3.0f * my * ay2 + 2.0f * my3;
    float uy4 = ay4 - 4.0f * my * ay3 + 6.0f * my2 * ay2 - 3.0f * my4;
    float uy5 = ay5 - 5.0f * my * ay4 + 10.0f * my2 * ay3 - 10.0f * my3 * ay2 + 4.0f * my5;

    float d1 = mx - my;
    float d2 = ux2 - uy2;
    float d3 = ux3 - uy3;
    float d4 = ux4 - uy4;
    float d5 = ux5 - uy5;

    float c1 = d1 * d1, c2 = d2 * d2, c3 = d3 * d3, c4 = d4 * d4, c5 = d5 * d5;

    #pragma unroll
    for (int o = 16; o > 0; o >>= 1) {
        c1 += __shfl_xor_sync(0xffffffffu, c1, o);
        c2 += __shfl_xor_sync(0xffffffffu, c2, o);
        c3 += __shfl_xor_sync(0xffffffffu, c3, o);
        c4 += __shfl_xor_sync(0xffffffffu, c4, o);
        c5 += __shfl_xor_sync(0xffffffffu, c5, o);
    }

    __shared__ float smf[8][5];
    if ((ch & 31) == 0) {
        int wf = ch >> 5;
        smf[wf][0] = c1; smf[wf][1] = c2; smf[wf][2] = c3;
        smf[wf][3] = c4; smf[wf][4] = c5;
    }
    __syncthreads();

    if (ch == 0) {
        float R1 = 0, R2 = 0, R3 = 0, R4 = 0, R5 = 0;
        #pragma unroll
        for (int ww = 0; ww < 8; ++ww) {
            R1 += smf[ww][0]; R2 += smf[ww][1]; R3 += smf[ww][2];
            R4 += smf[ww][3]; R5 += smf[ww][4];
        }
        out[0] = sqrtf(R1) + sqrtf(R2) + sqrtf(R3) + sqrtf(R4) + sqrtf(R5);
        g_count = 0;   // reset for next graph replay
    }
}

extern "C" void kernel_launch(void* const* d_in, const int* in_sizes, int n_in,
                              void* d_out, int out_size) {
    const float* x = (const float*)d_in[0];
    const float* y = (const float*)d_in[1];
    float* out = (float*)d_out;

    k_style<<<NBLK, 256>>>(x, y, out);
}

// round 5
// speedup vs baseline: 1.4217x; 1.0007x over previous
#include <cuda_runtime.h>

// StyleLoss: loss = sum_{k=1..5} sqrt( sum_c (mu_k_x[c] - mu_k_y[c])^2 )
// mu_1 = per-channel mean, mu_k (k>=2) = k-th central moment over (B,H,W).
// Shape fixed: (8, 256, 128, 128) fp32.
//
// SINGLE kernel: each of 2048 blocks computes raw-moment sums E-hat[x^k],
// k=1..5, for one (b,c) slab (packed f32x2 math, depth-2 load prefetch for
// MLP), writes 10 partials k-major, and the LAST block (atomic ticket)
// reduces over b, converts raw->central moments, and emits the loss.

#define NCHAN   256
#define NB      8
#define HW      (128 * 128)          // 16384 contiguous floats per (b,c) slab
#define NBLK    (NCHAN * NB)         // 2048 blocks
#define NPERCH  ((float)(NB * HW))   // 131072 elements per channel

__device__ float g_partial[10 * NBLK];   // [k][bid]
__device__ int   g_count = 0;

// ---- packed f32x2 helpers ------------------------------------------------
typedef unsigned long long u64;

#define MUL2(d, a, b) \
    asm("mul.rn.f32x2 %0, %1, %2;" : "=l"(d) : "l"(a), "l"(b))
#define ADD2(d, a, b) \
    asm("add.rn.f32x2 %0, %1, %2;" : "=l"(d) : "l"(a), "l"(b))
#define FMA2(d, a, b, c) \
    asm("fma.rn.f32x2 %0, %1, %2, %3;" : "=l"(d) : "l"(a), "l"(b), "l"(c))
#define PACK2(d, lo, hi) \
    asm("mov.b64 %0, {%1, %2};" : "=l"(d) : "f"(lo), "f"(hi))
#define UNPACK2(lo, hi, s) \
    asm("mov.b64 {%0, %1}, %2;" : "=f"(lo), "=f"(hi) : "l"(s))

// 2 MUL2 + 3 ADD2 + 2 FMA2 = 7 packed ops per 2 elements.
#define ACCP(p, A1, A2, A3, A4, A5)          \
    do {                                     \
        u64 _p2, _p4;                        \
        MUL2(_p2, (p), (p));                 \
        MUL2(_p4, _p2, _p2);                 \
        ADD2(A1, A1, (p));                   \
        ADD2(A2, A2, _p2);                   \
        FMA2(A3, _p2, (p), A3);              \
        ADD2(A4, A4, _p4);                   \
        FMA2(A5, _p4, (p), A5);              \
    } while (0)

__global__ __launch_bounds__(256, 3)
void k_style(const float* __restrict__ x, const float* __restrict__ y,
             float* __restrict__ out) {
    const int bid = blockIdx.x;
    const int c = bid >> 3;          // channel
    const int b = bid & 7;           // batch
    const size_t base = ((size_t)b * NCHAN + (size_t)c) * HW;
    const float4* __restrict__ xp = reinterpret_cast<const float4*>(x + base);
    const float4* __restrict__ yp = reinterpret_cast<const float4*>(y + base);

    const int tid = threadIdx.x;

    u64 S1 = 0, S2 = 0, S3 = 0, S4 = 0, S5 = 0;   // x raw-moment sums (2 lanes)
    u64 T1 = 0, T2 = 0, T3 = 0, T4 = 0, T5 = 0;   // y raw-moment sums

    // 4096 float4 per slab per tensor; 256 threads -> 16 float4 each.
    // Depth-2 prefetch: iteration i+1's loads issue before iteration i's
    // accumulation, keeping >=4 LDG.128 in flight per warp.
    float4 xa = __ldcs(xp + tid);
    float4 ya = __ldcs(yp + tid);

    #pragma unroll
    for (int i = 0; i < 16; ++i) {
        float4 xb, yb;
        if (i < 15) {
            xb = __ldcs(xp + tid + ((i + 1) << 8));
            yb = __ldcs(yp + tid + ((i + 1) << 8));
        }
        u64 pa, pb, qa, qb;
        PACK2(pa, xa.x, xa.y);
        PACK2(pb, xa.z, xa.w);
        PACK2(qa, ya.x, ya.y);
        PACK2(qb, ya.z, ya.w);
        ACCP(pa, S1, S2, S3, S4, S5);
        ACCP(pb, S1, S2, S3, S4, S5);
        ACCP(qa, T1, T2, T3, T4, T5);
        ACCP(qb, T1, T2, T3, T4, T5);
        if (i < 15) { xa = xb; ya = yb; }
    }

    // Collapse packed lanes to scalars.
    float s0, s1, s2, s3, s4, t0, t1, t2, t3, t4;
    {
        float lo, hi;
        UNPACK2(lo, hi, S1); s0 = lo + hi;
        UNPACK2(lo, hi, S2); s1 = lo + hi;
        UNPACK2(lo, hi, S3); s2 = lo + hi;
        UNPACK2(lo, hi, S4); s3 = lo + hi;
        UNPACK2(lo, hi, S5); s4 = lo + hi;
        UNPACK2(lo, hi, T1); t0 = lo + hi;
        UNPACK2(lo, hi, T2); t1 = lo + hi;
        UNPACK2(lo, hi, T3); t2 = lo + hi;
        UNPACK2(lo, hi, T4); t3 = lo + hi;
        UNPACK2(lo, hi, T5); t4 = lo + hi;
    }

    // Warp reduce all 10 accumulators.
    #pragma unroll
    for (int o = 16; o > 0; o >>= 1) {
        s0 += __shfl_xor_sync(0xffffffffu, s0, o);
        s1 += __shfl_xor_sync(0xffffffffu, s1, o);
        s2 += __shfl_xor_sync(0xffffffffu, s2, o);
        s3 += __shfl_xor_sync(0xffffffffu, s3, o);
        s4 += __shfl_xor_sync(0xffffffffu, s4, o);
        t0 += __shfl_xor_sync(0xffffffffu, t0, o);
        t1 += __shfl_xor_sync(0xffffffffu, t1, o);
        t2 += __shfl_xor_sync(0xffffffffu, t2, o);
        t3 += __shfl_xor_sync(0xffffffffu, t3, o);
        t4 += __shfl_xor_sync(0xffffffffu, t4, o);
    }

    __shared__ float smr[8][10];
    const int w = tid >> 5;
    if ((tid & 31) == 0) {
        smr[w][0] = s0; smr[w][1] = s1; smr[w][2] = s2; smr[w][3] = s3; smr[w][4] = s4;
        smr[w][5] = t0; smr[w][6] = t1; smr[w][7] = t2; smr[w][8] = t3; smr[w][9] = t4;
    }
    __syncthreads();

    if (tid < 10) {
        float a = 0.f;
        #pragma unroll
        for (int ww = 0; ww < 8; ++ww) a += smr[ww][tid];
        // k-major: channel c's 8 batch-partials for moment k are contiguous
        // at g_partial[k*NBLK + c*8].
        g_partial[tid * NBLK + bid] = a;
    }

    // ---- last-block finalize (threadFenceReduction pattern) --------------
    __shared__ int is_last;
    __threadfence();
    __syncthreads();
    if (tid == 0) {
        int v = atomicAdd(&g_count, 1);
        is_last = (v == NBLK - 1) ? 1 : 0;
    }
    __syncthreads();
    if (!is_last) return;

    const int ch = tid;              // one thread per channel

    float a[10];
    #pragma unroll
    for (int k = 0; k < 10; ++k) {
        const float4* p =
            reinterpret_cast<const float4*>(&g_partial[k * NBLK + ch * 8]);
        float4 u = p[0];
        float4 v = p[1];
        a[k] = ((u.x + u.y) + (u.z + u.w)) + ((v.x + v.y) + (v.z + v.w));
    }

    const float invN = 1.0f / NPERCH;
    float ax1 = a[0] * invN, ax2 = a[1] * invN, ax3 = a[2] * invN,
          ax4 = a[3] * invN, ax5 = a[4] * invN;
    float ay1 = a[5] * invN, ay2 = a[6] * invN, ay3 = a[7] * invN,
          ay4 = a[8] * invN, ay5 = a[9] * invN;

    // Central moments from raw moments (binomial identities).
    float mx = ax1, my = ay1;
    float mx2 = mx * mx, mx3 = mx2 * mx, mx4 = mx2 * mx2, mx5 = mx4 * mx;
    float my2 = my * my, my3 = my2 * my, my4 = my2 * my2, my5 = my4 * my;

    float ux2 = ax2 - mx2;
    float ux3 = ax3 - 3.0f * mx * ax2 + 2.0f * mx3;
    float ux4 = ax4 - 4.0f * mx * ax3 + 6.0f * mx2 * ax2 - 3.0f * mx4;
    float ux5 = ax5 - 5.0f * mx * ax4 + 10.0f * mx2 * ax3 - 10.0f * mx3 * ax2 + 4.0f * mx5;

    float uy2 = ay2 - my2;
    float uy3 = ay3 - 3.0f * my * ay2 + 2.0f * my3;
    float uy4 = ay4 - 4.0f * my * ay3 + 6.0f * my2 * ay2 - 3.0f * my4;
    float uy5 = ay5 - 5.0f * my * ay4 + 10.0f * my2 * ay3 - 10.0f * my3 * ay2 + 4.0f * my5;

    float d1 = mx - my;
    float d2 = ux2 - uy2;
    float d3 = ux3 - uy3;
    float d4 = ux4 - uy4;
    float d5 = ux5 - uy5;

    float c1 = d1 * d1, c2 = d2 * d2, c3 = d3 * d3, c4 = d4 * d4, c5 = d5 * d5;

    #pragma unroll
    for (int o = 16; o > 0; o >>= 1) {
        c1 += __shfl_xor_sync(0xffffffffu, c1, o);
        c2 += __shfl_xor_sync(0xffffffffu, c2, o);
        c3 += __shfl_xor_sync(0xffffffffu, c3, o);
        c4 += __shfl_xor_sync(0xffffffffu, c4, o);
        c5 += __shfl_xor_sync(0xffffffffu, c5, o);
    }

    __shared__ float smf[8][5];
    if ((ch & 31) == 0) {
        int wf = ch >> 5;
        smf[wf][0] = c1; smf[wf][1] = c2; smf[wf][2] = c3;
        smf[wf][3] = c4; smf[wf][4] = c5;
    }
    __syncthreads();

    if (ch == 0) {
        float R1 = 0, R2 = 0, R3 = 0, R4 = 0, R5 = 0;
        #pragma unroll
        for (int ww = 0; ww < 8; ++ww) {
            R1 += smf[ww][0]; R2 += smf[ww][1]; R3 += smf[ww][2];
            R4 += smf[ww][3]; R5 += smf[ww][4];
        }
        out[0] = sqrtf(R1) + sqrtf(R2) + sqrtf(R3) + sqrtf(R4) + sqrtf(R5);
        g_count = 0;   // reset for next graph replay
    }
}

extern "C" void kernel_launch(void* const* d_in, const int* in_sizes, int n_in,
                              void* d_out, int out_size) {
    const float* x = (const float*)d_in[0];
    const float* y = (const float*)d_in[1];
    float* out = (float*)d_out;

    k_style<<<NBLK, 256>>>(x, y, out);
}